// round 1
// baseline (speedup 1.0000x reference)
#include <cuda_runtime.h>
#include <math.h>

// Problem constants
#define B_   4
#define E_   32
#define D_   1024
#define NH_  16
#define NP_  4
#define LQ_  1024          // E*E
#define DH_  64            // D/NH

// ---------------------------------------------------------------------------
// Scratch (static device globals; allocation APIs are forbidden)
// ---------------------------------------------------------------------------
__device__ float g_fn   [B_ * 4 * LQ_ * D_];   // 64 MB  LN(concat srcs)
__device__ float g_qn   [B_ * LQ_ * D_];       // 16 MB  LN(src3)
__device__ float g_val  [B_ * 4 * LQ_ * D_];   // 64 MB  CA value
__device__ float g_off  [B_ * LQ_ * 512];      //  8 MB  CA offsets
__device__ float g_aw   [B_ * LQ_ * 256];      //  4 MB  CA attn weights
__device__ float g_samp [B_ * LQ_ * D_];       // 16 MB  CA sampled
__device__ float g_attn [B_ * LQ_ * D_];       // 16 MB  CA output
__device__ float g_attn1[B_ * LQ_ * D_];       // 16 MB  LN(attn)
__device__ float g_val2 [B_ * LQ_ * D_];       // 16 MB  SA value
__device__ float g_off2 [B_ * LQ_ * 128];      //  2 MB
__device__ float g_aw2  [B_ * LQ_ * 64];       //  1 MB
__device__ float g_samp2[B_ * LQ_ * D_];       // 16 MB
__device__ float g_attn2[B_ * LQ_ * D_];       // 16 MB

// ---------------------------------------------------------------------------
// LayerNorm: one block per row of 1024 floats.
// Handles the concat-remap: input row r = batch*in_rpb + rr maps to output
// row batch*out_rpb + out_off + rr.
// ---------------------------------------------------------------------------
__global__ void __launch_bounds__(256) ln_kernel(
    const float* __restrict__ in, const float* __restrict__ g,
    const float* __restrict__ b, float* __restrict__ out,
    int in_rpb, int out_rpb, int out_off)
{
    __shared__ float red[16];
    int r = blockIdx.x;
    int bb = r / in_rpb;
    int rr = r - bb * in_rpb;
    const float4* x4 = (const float4*)(in + (size_t)r * D_);
    float4* y4 = (float4*)(out + ((size_t)bb * out_rpb + out_off + rr) * D_);

    int t = threadIdx.x;
    float4 v = x4[t];
    float s  = v.x + v.y + v.z + v.w;
    float ss = v.x * v.x + v.y * v.y + v.z * v.z + v.w * v.w;
    #pragma unroll
    for (int o = 16; o; o >>= 1) {
        s  += __shfl_xor_sync(0xFFFFFFFFu, s,  o);
        ss += __shfl_xor_sync(0xFFFFFFFFu, ss, o);
    }
    int warp = t >> 5, lane = t & 31;
    if (lane == 0) { red[warp] = s; red[8 + warp] = ss; }
    __syncthreads();
    if (t == 0) {
        float S = 0.f, SS = 0.f;
        #pragma unroll
        for (int i = 0; i < 8; i++) { S += red[i]; SS += red[8 + i]; }
        red[0] = S; red[8] = SS;
    }
    __syncthreads();
    float mean = red[0] * (1.0f / D_);
    float var  = red[8] * (1.0f / D_) - mean * mean;
    float inv  = rsqrtf(var + 1e-6f);

    float4 gg = ((const float4*)g)[t];
    float4 bv = ((const float4*)b)[t];
    float4 o;
    o.x = (v.x - mean) * inv * gg.x + bv.x;
    o.y = (v.y - mean) * inv * gg.y + bv.y;
    o.z = (v.z - mean) * inv * gg.z + bv.z;
    o.w = (v.w - mean) * inv * gg.w + bv.w;
    y4[t] = o;
}

// ---------------------------------------------------------------------------
// SGEMM  C(M,N) = A(M,K) @ W(N,K)^T + bias(N)
// 64x64 tile, BK=16, 256 threads, 4x4 per thread. Requires M%64==0, N%64==0,
// K%16==0 (all satisfied here).
// ---------------------------------------------------------------------------
__global__ void __launch_bounds__(256) gemm_nt(
    const float* __restrict__ A, const float* __restrict__ W,
    const float* __restrict__ bias, float* __restrict__ C,
    int M, int N, int K)
{
    __shared__ float As[16][64];
    __shared__ float Ws[16][64];

    int tid = threadIdx.x;
    int tx = tid & 15;        // 0..15 -> N direction
    int ty = tid >> 4;        // 0..15 -> M direction
    int bm = blockIdx.y * 64;
    int bn = blockIdx.x * 64;

    int lr = tid >> 2;          // 0..63 row within tile
    int lc = (tid & 3) << 2;    // 0,4,8,12 col within K-tile

    const float* Ag = A + (size_t)(bm + lr) * K + lc;
    const float* Wg = W + (size_t)(bn + lr) * K + lc;

    float acc[4][4] = {};

    for (int k0 = 0; k0 < K; k0 += 16) {
        float4 a4 = *(const float4*)(Ag + k0);
        float4 w4 = *(const float4*)(Wg + k0);
        As[lc + 0][lr] = a4.x; As[lc + 1][lr] = a4.y;
        As[lc + 2][lr] = a4.z; As[lc + 3][lr] = a4.w;
        Ws[lc + 0][lr] = w4.x; Ws[lc + 1][lr] = w4.y;
        Ws[lc + 2][lr] = w4.z; Ws[lc + 3][lr] = w4.w;
        __syncthreads();
        #pragma unroll
        for (int k = 0; k < 16; k++) {
            float4 av = *(const float4*)&As[k][ty * 4];
            float4 wv = *(const float4*)&Ws[k][tx * 4];
            float a[4] = {av.x, av.y, av.z, av.w};
            float w[4] = {wv.x, wv.y, wv.z, wv.w};
            #pragma unroll
            for (int i = 0; i < 4; i++)
                #pragma unroll
                for (int j = 0; j < 4; j++)
                    acc[i][j] += a[i] * w[j];
        }
        __syncthreads();
    }

    float4 bvec = *(const float4*)&bias[bn + tx * 4];
    float bj[4] = {bvec.x, bvec.y, bvec.z, bvec.w};
    #pragma unroll
    for (int i = 0; i < 4; i++) {
        float4 o;
        o.x = acc[i][0] + bj[0];
        o.y = acc[i][1] + bj[1];
        o.z = acc[i][2] + bj[2];
        o.w = acc[i][3] + bj[3];
        *(float4*)&C[(size_t)(bm + ty * 4 + i) * N + bn + tx * 4] = o;
    }
}

// ---------------------------------------------------------------------------
// Softmax over P contiguous entries per (b,q,h). One thread per row.
// ---------------------------------------------------------------------------
__global__ void softmax_kernel(float* __restrict__ aw, int P, int total)
{
    int i = blockIdx.x * blockDim.x + threadIdx.x;
    if (i >= total) return;
    float* p = aw + (size_t)i * P;
    float m = -1e30f;
    for (int j = 0; j < P; j++) m = fmaxf(m, p[j]);
    float s = 0.f;
    for (int j = 0; j < P; j++) { float e = __expf(p[j] - m); p[j] = e; s += e; }
    float inv = 1.0f / s;
    for (int j = 0; j < P; j++) p[j] *= inv;
}

// ---------------------------------------------------------------------------
// Deformable sampling. One block per (b,q): 16 warps = 16 heads; each lane
// handles 2 of the 64 head-dims via float2 gathers (256B per warp per corner).
// value layout: (B, NL*1024, D) with D = h*64+d. All levels are 32x32.
// ---------------------------------------------------------------------------
template<int NL>
__global__ void __launch_bounds__(512) deform_sample(
    const float* __restrict__ value, const float* __restrict__ off,
    const float* __restrict__ attw, float* __restrict__ out)
{
    int bq = blockIdx.x;
    int b = bq >> 10, q = bq & 1023;
    int h = threadIdx.x >> 5, lane = threadIdx.x & 31;

    float rx = ((q & 31) + 0.5f) * 0.03125f;
    float ry = ((q >> 5) + 0.5f) * 0.03125f;

    const float* offp = off  + ((size_t)bq * NH_ + h) * (NL * NP_ * 2);
    const float* awp  = attw + ((size_t)bq * NH_ + h) * (NL * NP_);
    const float* vbase = value + (size_t)b * (NL * 1024) * D_ + h * DH_;

    float2 acc = make_float2(0.f, 0.f);

    #pragma unroll
    for (int l = 0; l < NL; l++) {
        #pragma unroll
        for (int p = 0; p < NP_; p++) {
            int s = l * NP_ + p;
            float ox = offp[s * 2 + 0];
            float oy = offp[s * 2 + 1];
            float a  = awp[s];
            // loc = ref + off/32 ; x = loc_x*32 - 0.5
            float x = (rx + ox * 0.03125f) * 32.0f - 0.5f;
            float y = (ry + oy * 0.03125f) * 32.0f - 0.5f;
            float x0f = floorf(x), y0f = floorf(y);
            float wx1 = x - x0f, wy1 = y - y0f;
            int x0 = (int)x0f, y0 = (int)y0f;
            #pragma unroll
            for (int dy = 0; dy < 2; dy++) {
                int yi = y0 + dy;
                if ((unsigned)yi >= 32u) continue;
                float wy = dy ? wy1 : (1.0f - wy1);
                #pragma unroll
                for (int dx = 0; dx < 2; dx++) {
                    int xi = x0 + dx;
                    if ((unsigned)xi >= 32u) continue;
                    float w = (dx ? wx1 : (1.0f - wx1)) * wy * a;
                    const float2* vp = (const float2*)(vbase +
                        ((size_t)l * 1024 + yi * 32 + xi) * D_);
                    float2 v = vp[lane];
                    acc.x += v.x * w;
                    acc.y += v.y * w;
                }
            }
        }
    }
    ((float2*)(out + (size_t)bq * D_ + h * DH_))[lane] = acc;
}

// ---------------------------------------------------------------------------
// Final residual combine: out = src3 + g1*(attn + g2*attn2)
// ---------------------------------------------------------------------------
__global__ void final_kernel(
    const float* __restrict__ src3, const float* __restrict__ attn,
    const float* __restrict__ attn2, const float* __restrict__ g1,
    const float* __restrict__ g2, float* __restrict__ out, int n4)
{
    int i = blockIdx.x * blockDim.x + threadIdx.x;
    if (i >= n4) return;
    int d4 = i & (D_ / 4 - 1);
    float4 s = ((const float4*)src3)[i];
    float4 a = ((const float4*)attn)[i];
    float4 a2 = ((const float4*)attn2)[i];
    float4 G1 = ((const float4*)g1)[d4];
    float4 G2 = ((const float4*)g2)[d4];
    float4 o;
    o.x = s.x + G1.x * (a.x + G2.x * a2.x);
    o.y = s.y + G1.y * (a.y + G2.y * a2.y);
    o.z = s.z + G1.z * (a.z + G2.z * a2.z);
    o.w = s.w + G1.w * (a.w + G2.w * a2.w);
    ((float4*)out)[i] = o;
}

// ---------------------------------------------------------------------------
// Host launcher
// ---------------------------------------------------------------------------
extern "C" void kernel_launch(void* const* d_in, const int* in_sizes, int n_in,
                              void* d_out, int out_size)
{
    const float* src[4] = {(const float*)d_in[0], (const float*)d_in[1],
                           (const float*)d_in[2], (const float*)d_in[3]};
    const float* qn_g = (const float*)d_in[4];
    const float* qn_b = (const float*)d_in[5];
    const float* fn_g = (const float*)d_in[6];
    const float* fn_b = (const float*)d_in[7];
    const float* n1_g = (const float*)d_in[8];
    const float* n1_b = (const float*)d_in[9];
    const float* gamma1 = (const float*)d_in[10];
    const float* gamma2 = (const float*)d_in[11];
    const float* ca_vw = (const float*)d_in[12];
    const float* ca_vb = (const float*)d_in[13];
    const float* ca_ow = (const float*)d_in[14];
    const float* ca_ob = (const float*)d_in[15];
    const float* ca_aw = (const float*)d_in[16];
    const float* ca_ab = (const float*)d_in[17];
    const float* ca_pw = (const float*)d_in[18];
    const float* ca_pb = (const float*)d_in[19];
    const float* sa_vw = (const float*)d_in[20];
    const float* sa_vb = (const float*)d_in[21];
    const float* sa_ow = (const float*)d_in[22];
    const float* sa_ob = (const float*)d_in[23];
    const float* sa_aw = (const float*)d_in[24];
    const float* sa_ab = (const float*)d_in[25];
    const float* sa_pw = (const float*)d_in[26];
    const float* sa_pb = (const float*)d_in[27];

    float *fn, *qn, *val, *off, *aw, *samp, *attn, *attn1;
    float *val2, *off2, *aw2, *samp2, *attn2;
    cudaGetSymbolAddress((void**)&fn,    g_fn);
    cudaGetSymbolAddress((void**)&qn,    g_qn);
    cudaGetSymbolAddress((void**)&val,   g_val);
    cudaGetSymbolAddress((void**)&off,   g_off);
    cudaGetSymbolAddress((void**)&aw,    g_aw);
    cudaGetSymbolAddress((void**)&samp,  g_samp);
    cudaGetSymbolAddress((void**)&attn,  g_attn);
    cudaGetSymbolAddress((void**)&attn1, g_attn1);
    cudaGetSymbolAddress((void**)&val2,  g_val2);
    cudaGetSymbolAddress((void**)&off2,  g_off2);
    cudaGetSymbolAddress((void**)&aw2,   g_aw2);
    cudaGetSymbolAddress((void**)&samp2, g_samp2);
    cudaGetSymbolAddress((void**)&attn2, g_attn2);

    const int ROWS = B_ * LQ_;             // 4096
    const int FROWS = B_ * 4 * LQ_;        // 16384

    // 1) LayerNorm feat (concat of 4 srcs) and query
    for (int l = 0; l < 4; l++)
        ln_kernel<<<ROWS, 256>>>(src[l], fn_g, fn_b, fn, LQ_, 4 * LQ_, l * LQ_);
    ln_kernel<<<ROWS, 256>>>(src[3], qn_g, qn_b, qn, LQ_, LQ_, 0);

    // 2) Cross-attention MSDeform
    gemm_nt<<<dim3(1024 / 64, FROWS / 64), 256>>>(fn, ca_vw, ca_vb, val, FROWS, 1024, 1024);
    gemm_nt<<<dim3(512 / 64,  ROWS / 64), 256>>>(qn, ca_ow, ca_ob, off, ROWS, 512, 1024);
    gemm_nt<<<dim3(256 / 64,  ROWS / 64), 256>>>(qn, ca_aw, ca_ab, aw,  ROWS, 256, 1024);
    softmax_kernel<<<(ROWS * NH_ + 255) / 256, 256>>>(aw, 16, ROWS * NH_);
    deform_sample<4><<<ROWS, 512>>>(val, off, aw, samp);
    gemm_nt<<<dim3(1024 / 64, ROWS / 64), 256>>>(samp, ca_pw, ca_pb, attn, ROWS, 1024, 1024);

    // 3) LN + self-attention MSDeform
    ln_kernel<<<ROWS, 256>>>(attn, n1_g, n1_b, attn1, LQ_, LQ_, 0);
    gemm_nt<<<dim3(1024 / 64, ROWS / 64), 256>>>(attn1, sa_vw, sa_vb, val2, ROWS, 1024, 1024);
    gemm_nt<<<dim3(128 / 64,  ROWS / 64), 256>>>(attn1, sa_ow, sa_ob, off2, ROWS, 128, 1024);
    gemm_nt<<<dim3(64 / 64,   ROWS / 64), 256>>>(attn1, sa_aw, sa_ab, aw2,  ROWS, 64, 1024);
    softmax_kernel<<<(ROWS * NH_ + 255) / 256, 256>>>(aw2, 4, ROWS * NH_);
    deform_sample<1><<<ROWS, 512>>>(val2, off2, aw2, samp2);
    gemm_nt<<<dim3(1024 / 64, ROWS / 64), 256>>>(samp2, sa_pw, sa_pb, attn2, ROWS, 1024, 1024);

    // 4) Final combine
    final_kernel<<<(ROWS * D_ / 4 + 255) / 256, 256>>>(
        src[3], attn, attn2, gamma1, gamma2, (float*)d_out, ROWS * D_ / 4);
}

// round 3
// speedup vs baseline: 3.0340x; 3.0340x over previous
#include <cuda_runtime.h>
#include <math.h>
#include <stdint.h>

// Problem constants
#define B_   4
#define E_   32
#define D_   1024
#define NH_  16
#define NP_  4
#define LQ_  1024          // E*E
#define DH_  64            // D/NH

// ---------------------------------------------------------------------------
// Scratch (static device globals; allocation APIs are forbidden)
// ---------------------------------------------------------------------------
__device__ float g_fn   [B_ * 4 * LQ_ * D_];   // 64 MB  LN(concat srcs)
__device__ float g_qn   [B_ * LQ_ * D_];       // 16 MB  LN(src3)
__device__ float g_val  [B_ * 4 * LQ_ * D_];   // 64 MB  CA value
__device__ float g_off  [B_ * LQ_ * 512];      //  8 MB  CA offsets
__device__ float g_aw   [B_ * LQ_ * 256];      //  4 MB  CA attn weights
__device__ float g_samp [B_ * LQ_ * D_];       // 16 MB  CA sampled
__device__ float g_attn [B_ * LQ_ * D_];       // 16 MB  CA output
__device__ float g_attn1[B_ * LQ_ * D_];       // 16 MB  LN(attn)
__device__ float g_val2 [B_ * LQ_ * D_];       // 16 MB  SA value
__device__ float g_off2 [B_ * LQ_ * 128];      //  2 MB
__device__ float g_aw2  [B_ * LQ_ * 64];       //  1 MB
__device__ float g_samp2[B_ * LQ_ * D_];       // 16 MB
__device__ float g_attn2[B_ * LQ_ * D_];       // 16 MB

// ---------------------------------------------------------------------------
// Helpers
// ---------------------------------------------------------------------------
__device__ __forceinline__ uint32_t smem_u32(const void* p) {
    uint32_t a;
    asm("{ .reg .u64 t; cvta.to.shared.u64 t, %1; cvt.u32.u64 %0, t; }"
        : "=r"(a) : "l"(p));
    return a;
}
__device__ __forceinline__ void cp16(uint32_t s, const void* g) {
    asm volatile("cp.async.cg.shared.global [%0], [%1], 16;\n" :: "r"(s), "l"(g));
}
__device__ __forceinline__ void cp16p(uint32_t s, const void* g, uint32_t nbytes) {
    asm volatile("cp.async.cg.shared.global [%0], [%1], 16, %2;\n"
                 :: "r"(s), "l"(g), "r"(nbytes));
}
__device__ __forceinline__ uint32_t cvt_tf32(float f) {
    uint32_t o;
    asm("cvt.rna.tf32.f32 %0, %1;" : "=r"(o) : "f"(f));
    return o;
}
__device__ __forceinline__ void mma_tf32(float* d, const uint32_t* a, const uint32_t* b) {
    asm volatile(
        "mma.sync.aligned.m16n8k8.row.col.f32.tf32.tf32.f32 "
        "{%0,%1,%2,%3}, {%4,%5,%6,%7}, {%8,%9}, {%0,%1,%2,%3};"
        : "+f"(d[0]), "+f"(d[1]), "+f"(d[2]), "+f"(d[3])
        : "r"(a[0]), "r"(a[1]), "r"(a[2]), "r"(a[3]), "r"(b[0]), "r"(b[1]));
}

// ---------------------------------------------------------------------------
// TF32 tensor-core GEMM:  C(M,N) = A(M,K=1024) @ W(N,K=1024)^T + bias(N)
// Block 128x128x32, 4 warps of 64x64, mma.sync m16n8k8 tf32, 2-stage cp.async.
// Handles N < 128 via zero-fill loads + predicated stores. Requires M%128==0.
// ---------------------------------------------------------------------------
#define LDSS 36          // smem row stride in floats (32 + 4 pad)
#define STG  (128*LDSS)  // floats per stage (4608)

__global__ void __launch_bounds__(128) gemm_tf32(
    const float* __restrict__ A, const float* __restrict__ W,
    const float* __restrict__ bias, float* __restrict__ C, int N)
{
    extern __shared__ float sm[];
    float* Asm = sm;               // 2 stages
    float* Bsm = sm + 2 * STG;     // 2 stages

    const int K = 1024, NIT = 32;
    int tid = threadIdx.x, wid = tid >> 5, lane = tid & 31;
    int wm = wid & 1, wn = wid >> 1;      // warp tile 64x64 in 2x2 arrangement
    int g = lane >> 2, c = lane & 3;
    int bm = blockIdx.y * 128, bn = blockIdx.x * 128;

    uint32_t abase = smem_u32(Asm), bbase = smem_u32(Bsm);

    float acc[4][8][4];
    #pragma unroll
    for (int mt = 0; mt < 4; mt++)
        #pragma unroll
        for (int nt = 0; nt < 8; nt++)
            #pragma unroll
            for (int i = 0; i < 4; i++) acc[mt][nt][i] = 0.f;

    int rowA = tid >> 3, jA = tid & 7;    // 128 threads cover 1024 16B chunks in 8 steps

    auto load_stage = [&](int s, int it) {
        int k0 = it * 32;
        #pragma unroll
        for (int i = 0; i < 8; ++i) {
            int row = rowA + i * 16;
            cp16(abase + (uint32_t)(s * STG + row * LDSS + jA * 4) * 4,
                 A + (size_t)(bm + row) * K + k0 + jA * 4);
        }
        #pragma unroll
        for (int i = 0; i < 8; ++i) {
            int row = rowA + i * 16;
            int srow = bn + row;
            const float* src = W + (size_t)(srow < N ? srow : 0) * K + k0 + jA * 4;
            cp16p(bbase + (uint32_t)(s * STG + row * LDSS + jA * 4) * 4,
                  src, srow < N ? 16u : 0u);
        }
        asm volatile("cp.async.commit_group;" ::: "memory");
    };

    load_stage(0, 0);
    load_stage(1, 1);

    for (int it = 0; it < NIT; ++it) {
        int s = it & 1;
        asm volatile("cp.async.wait_group 1;" ::: "memory");
        __syncthreads();

        const float* Ab = Asm + s * STG;
        const float* Bb = Bsm + s * STG;
        #pragma unroll
        for (int ks = 0; ks < 4; ks++) {
            uint32_t af[4][4], bf[8][2];
            int col = ks * 8 + c;
            #pragma unroll
            for (int mt = 0; mt < 4; mt++) {
                int r = wm * 64 + mt * 16 + g;
                af[mt][0] = cvt_tf32(Ab[r * LDSS + col]);
                af[mt][1] = cvt_tf32(Ab[(r + 8) * LDSS + col]);
                af[mt][2] = cvt_tf32(Ab[r * LDSS + col + 4]);
                af[mt][3] = cvt_tf32(Ab[(r + 8) * LDSS + col + 4]);
            }
            #pragma unroll
            for (int nt = 0; nt < 8; nt++) {
                int r = wn * 64 + nt * 8 + g;
                bf[nt][0] = cvt_tf32(Bb[r * LDSS + col]);
                bf[nt][1] = cvt_tf32(Bb[r * LDSS + col + 4]);
            }
            #pragma unroll
            for (int mt = 0; mt < 4; mt++)
                #pragma unroll
                for (int nt = 0; nt < 8; nt++)
                    mma_tf32(acc[mt][nt], af[mt], bf[nt]);
        }
        __syncthreads();
        if (it + 2 < NIT) load_stage(s, it + 2);
    }

    // Epilogue
    #pragma unroll
    for (int mt = 0; mt < 4; mt++) {
        int r0 = bm + wm * 64 + mt * 16 + g;
        #pragma unroll
        for (int nt = 0; nt < 8; nt++) {
            int colb = bn + wn * 64 + nt * 8;
            if (colb < N) {
                int cg = colb + 2 * c;
                float2 bv = *(const float2*)(bias + cg);
                float2 o0 = { acc[mt][nt][0] + bv.x, acc[mt][nt][1] + bv.y };
                float2 o1 = { acc[mt][nt][2] + bv.x, acc[mt][nt][3] + bv.y };
                *(float2*)(C + (size_t)r0 * N + cg) = o0;
                *(float2*)(C + (size_t)(r0 + 8) * N + cg) = o1;
            }
        }
    }
}

// ---------------------------------------------------------------------------
// LayerNorm: one block per row of 1024 floats (with concat remap).
// ---------------------------------------------------------------------------
__global__ void __launch_bounds__(256) ln_kernel(
    const float* __restrict__ in, const float* __restrict__ g,
    const float* __restrict__ b, float* __restrict__ out,
    int in_rpb, int out_rpb, int out_off)
{
    __shared__ float red[16];
    int r = blockIdx.x;
    int bb = r / in_rpb;
    int rr = r - bb * in_rpb;
    const float4* x4 = (const float4*)(in + (size_t)r * D_);
    float4* y4 = (float4*)(out + ((size_t)bb * out_rpb + out_off + rr) * D_);

    int t = threadIdx.x;
    float4 v = x4[t];
    float s  = v.x + v.y + v.z + v.w;
    float ss = v.x * v.x + v.y * v.y + v.z * v.z + v.w * v.w;
    #pragma unroll
    for (int o = 16; o; o >>= 1) {
        s  += __shfl_xor_sync(0xFFFFFFFFu, s,  o);
        ss += __shfl_xor_sync(0xFFFFFFFFu, ss, o);
    }
    int warp = t >> 5, lane = t & 31;
    if (lane == 0) { red[warp] = s; red[8 + warp] = ss; }
    __syncthreads();
    if (t == 0) {
        float S = 0.f, SS = 0.f;
        #pragma unroll
        for (int i = 0; i < 8; i++) { S += red[i]; SS += red[8 + i]; }
        red[0] = S; red[8] = SS;
    }
    __syncthreads();
    float mean = red[0] * (1.0f / D_);
    float var  = red[8] * (1.0f / D_) - mean * mean;
    float inv  = rsqrtf(var + 1e-6f);

    float4 gg = ((const float4*)g)[t];
    float4 bv = ((const float4*)b)[t];
    float4 o;
    o.x = (v.x - mean) * inv * gg.x + bv.x;
    o.y = (v.y - mean) * inv * gg.y + bv.y;
    o.z = (v.z - mean) * inv * gg.z + bv.z;
    o.w = (v.w - mean) * inv * gg.w + bv.w;
    y4[t] = o;
}

// ---------------------------------------------------------------------------
// Softmax over P contiguous entries per (b,q,h).
// ---------------------------------------------------------------------------
__global__ void softmax_kernel(float* __restrict__ aw, int P, int total)
{
    int i = blockIdx.x * blockDim.x + threadIdx.x;
    if (i >= total) return;
    float* p = aw + (size_t)i * P;
    float m = -1e30f;
    for (int j = 0; j < P; j++) m = fmaxf(m, p[j]);
    float s = 0.f;
    for (int j = 0; j < P; j++) { float e = __expf(p[j] - m); p[j] = e; s += e; }
    float inv = 1.0f / s;
    for (int j = 0; j < P; j++) p[j] *= inv;
}

// ---------------------------------------------------------------------------
// Deformable sampling: 1 block per (b,q), 16 warps = heads, float2 per lane.
// ---------------------------------------------------------------------------
template<int NL>
__global__ void __launch_bounds__(512) deform_sample(
    const float* __restrict__ value, const float* __restrict__ off,
    const float* __restrict__ attw, float* __restrict__ out)
{
    int bq = blockIdx.x;
    int b = bq >> 10, q = bq & 1023;
    int h = threadIdx.x >> 5, lane = threadIdx.x & 31;

    float rx = ((q & 31) + 0.5f) * 0.03125f;
    float ry = ((q >> 5) + 0.5f) * 0.03125f;

    const float* offp = off  + ((size_t)bq * NH_ + h) * (NL * NP_ * 2);
    const float* awp  = attw + ((size_t)bq * NH_ + h) * (NL * NP_);
    const float* vbase = value + (size_t)b * (NL * 1024) * D_ + h * DH_;

    float2 acc = make_float2(0.f, 0.f);

    #pragma unroll
    for (int l = 0; l < NL; l++) {
        #pragma unroll
        for (int p = 0; p < NP_; p++) {
            int s = l * NP_ + p;
            float ox = offp[s * 2 + 0];
            float oy = offp[s * 2 + 1];
            float a  = awp[s];
            float x = (rx + ox * 0.03125f) * 32.0f - 0.5f;
            float y = (ry + oy * 0.03125f) * 32.0f - 0.5f;
            float x0f = floorf(x), y0f = floorf(y);
            float wx1 = x - x0f, wy1 = y - y0f;
            int x0 = (int)x0f, y0 = (int)y0f;
            #pragma unroll
            for (int dy = 0; dy < 2; dy++) {
                int yi = y0 + dy;
                if ((unsigned)yi >= 32u) continue;
                float wy = dy ? wy1 : (1.0f - wy1);
                #pragma unroll
                for (int dx = 0; dx < 2; dx++) {
                    int xi = x0 + dx;
                    if ((unsigned)xi >= 32u) continue;
                    float w = (dx ? wx1 : (1.0f - wx1)) * wy * a;
                    const float2* vp = (const float2*)(vbase +
                        ((size_t)l * 1024 + yi * 32 + xi) * D_);
                    float2 v = vp[lane];
                    acc.x += v.x * w;
                    acc.y += v.y * w;
                }
            }
        }
    }
    ((float2*)(out + (size_t)bq * D_ + h * DH_))[lane] = acc;
}

// ---------------------------------------------------------------------------
// Final residual combine: out = src3 + g1*(attn + g2*attn2)
// ---------------------------------------------------------------------------
__global__ void final_kernel(
    const float* __restrict__ src3, const float* __restrict__ attn,
    const float* __restrict__ attn2, const float* __restrict__ g1,
    const float* __restrict__ g2, float* __restrict__ out, int n4)
{
    int i = blockIdx.x * blockDim.x + threadIdx.x;
    if (i >= n4) return;
    int d4 = i & (D_ / 4 - 1);
    float4 s = ((const float4*)src3)[i];
    float4 a = ((const float4*)attn)[i];
    float4 a2 = ((const float4*)attn2)[i];
    float4 G1 = ((const float4*)g1)[d4];
    float4 G2 = ((const float4*)g2)[d4];
    float4 o;
    o.x = s.x + G1.x * (a.x + G2.x * a2.x);
    o.y = s.y + G1.y * (a.y + G2.y * a2.y);
    o.z = s.z + G1.z * (a.z + G2.z * a2.z);
    o.w = s.w + G1.w * (a.w + G2.w * a2.w);
    ((float4*)out)[i] = o;
}

// ---------------------------------------------------------------------------
// Host launcher
// ---------------------------------------------------------------------------
extern "C" void kernel_launch(void* const* d_in, const int* in_sizes, int n_in,
                              void* d_out, int out_size)
{
    const float* src[4] = {(const float*)d_in[0], (const float*)d_in[1],
                           (const float*)d_in[2], (const float*)d_in[3]};
    const float* qn_g = (const float*)d_in[4];
    const float* qn_b = (const float*)d_in[5];
    const float* fn_g = (const float*)d_in[6];
    const float* fn_b = (const float*)d_in[7];
    const float* n1_g = (const float*)d_in[8];
    const float* n1_b = (const float*)d_in[9];
    const float* gamma1 = (const float*)d_in[10];
    const float* gamma2 = (const float*)d_in[11];
    const float* ca_vw = (const float*)d_in[12];
    const float* ca_vb = (const float*)d_in[13];
    const float* ca_ow = (const float*)d_in[14];
    const float* ca_ob = (const float*)d_in[15];
    const float* ca_aw = (const float*)d_in[16];
    const float* ca_ab = (const float*)d_in[17];
    const float* ca_pw = (const float*)d_in[18];
    const float* ca_pb = (const float*)d_in[19];
    const float* sa_vw = (const float*)d_in[20];
    const float* sa_vb = (const float*)d_in[21];
    const float* sa_ow = (const float*)d_in[22];
    const float* sa_ob = (const float*)d_in[23];
    const float* sa_aw = (const float*)d_in[24];
    const float* sa_ab = (const float*)d_in[25];
    const float* sa_pw = (const float*)d_in[26];
    const float* sa_pb = (const float*)d_in[27];

    float *fn, *qn, *val, *off, *aw, *samp, *attn, *attn1;
    float *val2, *off2, *aw2, *samp2, *attn2;
    cudaGetSymbolAddress((void**)&fn,    g_fn);
    cudaGetSymbolAddress((void**)&qn,    g_qn);
    cudaGetSymbolAddress((void**)&val,   g_val);
    cudaGetSymbolAddress((void**)&off,   g_off);
    cudaGetSymbolAddress((void**)&aw,    g_aw);
    cudaGetSymbolAddress((void**)&samp,  g_samp);
    cudaGetSymbolAddress((void**)&attn,  g_attn);
    cudaGetSymbolAddress((void**)&attn1, g_attn1);
    cudaGetSymbolAddress((void**)&val2,  g_val2);
    cudaGetSymbolAddress((void**)&off2,  g_off2);
    cudaGetSymbolAddress((void**)&aw2,   g_aw2);
    cudaGetSymbolAddress((void**)&samp2, g_samp2);
    cudaGetSymbolAddress((void**)&attn2, g_attn2);

    const int ROWS = B_ * LQ_;             // 4096
    const int SMEM = 4 * STG * 4;          // 73728 bytes

    cudaFuncSetAttribute(gemm_tf32, cudaFuncAttributeMaxDynamicSharedMemorySize, SMEM);

    // 1) LayerNorm feat (concat of 4 srcs) and query
    for (int l = 0; l < 4; l++)
        ln_kernel<<<ROWS, 256>>>(src[l], fn_g, fn_b, fn, LQ_, 4 * LQ_, l * LQ_);
    ln_kernel<<<ROWS, 256>>>(src[3], qn_g, qn_b, qn, LQ_, LQ_, 0);

    // 2) Cross-attention MSDeform
    gemm_tf32<<<dim3(8, 128), 128, SMEM>>>(fn, ca_vw, ca_vb, val, 1024);
    gemm_tf32<<<dim3(4, 32),  128, SMEM>>>(qn, ca_ow, ca_ob, off, 512);
    gemm_tf32<<<dim3(2, 32),  128, SMEM>>>(qn, ca_aw, ca_ab, aw,  256);
    softmax_kernel<<<(ROWS * NH_ + 255) / 256, 256>>>(aw, 16, ROWS * NH_);
    deform_sample<4><<<ROWS, 512>>>(val, off, aw, samp);
    gemm_tf32<<<dim3(8, 32),  128, SMEM>>>(samp, ca_pw, ca_pb, attn, 1024);

    // 3) LN + self-attention MSDeform
    ln_kernel<<<ROWS, 256>>>(attn, n1_g, n1_b, attn1, LQ_, LQ_, 0);
    gemm_tf32<<<dim3(8, 32),  128, SMEM>>>(attn1, sa_vw, sa_vb, val2, 1024);
    gemm_tf32<<<dim3(1, 32),  128, SMEM>>>(attn1, sa_ow, sa_ob, off2, 128);
    gemm_tf32<<<dim3(1, 32),  128, SMEM>>>(attn1, sa_aw, sa_ab, aw2,  64);
    softmax_kernel<<<(ROWS * NH_ + 255) / 256, 256>>>(aw2, 4, ROWS * NH_);
    deform_sample<1><<<ROWS, 512>>>(val2, off2, aw2, samp2);
    gemm_tf32<<<dim3(8, 32),  128, SMEM>>>(samp2, sa_pw, sa_pb, attn2, 1024);

    // 4) Final combine
    final_kernel<<<(ROWS * D_ / 4 + 255) / 256, 256>>>(
        src[3], attn, attn2, gamma1, gamma2, (float*)d_out, ROWS * D_ / 4);
}